// round 16
// baseline (speedup 1.0000x reference)
#include <cuda_runtime.h>
#include <cuda_fp16.h>
#include <cstdint>
#include <math.h>

// Problem constants
#define BDIM   4
#define TDIM   4096
#define DDIM   2048
#define DBDIM  512
#define BT     (BDIM * TDIM)   // 16384 tokens
#define EPSV   1e-6f

// ---------------- scratch (static device globals; no runtime allocation) ----
__device__ __half g_xh  [(size_t)BT * DDIM];         // fp16 x
__device__ __half g_winh[(size_t)DBDIM * DDIM];      // fp16 W_in
__device__ __half g_wkh [(size_t)DDIM * DBDIM];      // fp16 W_k
__device__ __half g_wvh [(size_t)DDIM * DBDIM];      // fp16 W_v
__device__ __half g_wch [(size_t)3 * DBDIM * DBDIM]; // fp16 combined mix W [1536,512]
__device__ __half g_zh  [(size_t)BT * DBDIM];        // fp16 bottleneck proj
__device__ __half g_zm  [(size_t)BT * 3 * DBDIM];    // fp16 z @ [M0|M1|M2]
__device__ __half g_yh  [(size_t)BT * DBDIM];        // fp16 mixed
__device__ __half g_vh  [(size_t)BT * DDIM];         // fp16 value proj
__device__ float  g_sxx [(size_t)BT];                // per-token sum x^2
__device__ float  g_pk2 [(size_t)16 * BT];           // per-colblock partial sum k^2
__device__ float  g_pxk [(size_t)16 * BT];           // per-colblock partial sum x*k
__device__ float  g_pv2 [(size_t)16 * BT];           // per-colblock partial sum v^2

// ---------------------------------------------------------------------------
// helpers
// ---------------------------------------------------------------------------
__device__ __forceinline__ uint32_t s2u(const void* p) {
    uint32_t a;
    asm("{ .reg .u64 t; cvta.to.shared.u64 t, %1; cvt.u32.u64 %0, t; }"
        : "=r"(a) : "l"(p));
    return a;
}

__device__ __forceinline__ void cp16(uint32_t dst, const void* src) {
    asm volatile("cp.async.cg.shared.global [%0], [%1], 16;" :: "r"(dst), "l"(src));
}
__device__ __forceinline__ void cp_commit() {
    asm volatile("cp.async.commit_group;" ::: "memory");
}
template<int N> __device__ __forceinline__ void cp_wait() {
    asm volatile("cp.async.wait_group %0;" :: "n"(N) : "memory");
}

__device__ __forceinline__ void ldmx4(uint32_t& r0, uint32_t& r1,
                                      uint32_t& r2, uint32_t& r3, uint32_t addr) {
    asm volatile("ldmatrix.sync.aligned.m8n8.x4.shared.b16 {%0,%1,%2,%3}, [%4];"
        : "=r"(r0), "=r"(r1), "=r"(r2), "=r"(r3) : "r"(addr));
}

// mma.sync m16n8k16 fp16 inputs, fp32 accumulate
__device__ __forceinline__ void mma_f16(float& c0, float& c1, float& c2, float& c3,
                                        uint32_t a0, uint32_t a1, uint32_t a2,
                                        uint32_t a3, uint32_t b0, uint32_t b1) {
    asm volatile(
        "mma.sync.aligned.m16n8k16.row.col.f32.f16.f16.f32 "
        "{%0,%1,%2,%3}, {%4,%5,%6,%7}, {%8,%9}, {%0,%1,%2,%3};"
        : "+f"(c0), "+f"(c1), "+f"(c2), "+f"(c3)
        : "r"(a0), "r"(a1), "r"(a2), "r"(a3), "r"(b0), "r"(b1));
}

// ---------------------------------------------------------------------------
// GEMM config (champion): 128x128x64 tile, 8 warps (4m x 2n), warp tile
// 32x64, 3-stage cp.async, 2 CTAs/SM, ldmatrix.x4 frags, 144B padded rows.
// ---------------------------------------------------------------------------
#define TBM    128
#define TBN    128
#define TBK    64
#define NSTG   3
#define LROWB  144
#define STG_B  (128 * LROWB)            // 18432 B
#define SOFF_B (NSTG * STG_B)
#define GEMM_SMEM (2 * NSTG * STG_B)    // 110592 B

#define GEMM_PROLOGUE_AND_MAINLOOP                                             \
    const int tid  = threadIdx.x;                                              \
    const int lane = tid & 31;                                                 \
    const int wid  = tid >> 5;                                                 \
    const int wm   = (wid & 3) * 32;                                           \
    const int wn   = (wid >> 2) * 64;                                          \
    const int g    = lane >> 2;                                                \
    const int tg   = lane & 3;                                                 \
    const uint32_t aoff = (uint32_t)(wm + (lane & 7) + ((lane >> 3) & 1) * 8)  \
                          * LROWB + ((lane >> 4) & 1) * 16;                    \
    const uint32_t boff = (uint32_t)(wn + (lane & 7) + ((lane >> 4) & 1) * 8)  \
                          * LROWB + ((lane >> 3) & 1) * 16;                    \
    const int bm = blockIdx.y * TBM;                                           \
    const int bn = blockIdx.x * TBN;                                           \
    const int num_k = K / TBK;                                                 \
    const __half* Abase = A + (size_t)bm * K;                                  \
    const __half* Wbase = W + (size_t)bn * K;                                  \
    auto load_stage = [&](int ks, int buf) {                                   \
        const __half* Ap = Abase + ks * TBK;                                   \
        const __half* Wp = Wbase + ks * TBK;                                   \
        uint32_t ab = sb + buf * STG_B;                                        \
        uint32_t bb = sb + SOFF_B + buf * STG_B;                               \
        _Pragma("unroll")                                                      \
        for (int i = 0; i < 4; i++) {                                          \
            int idx = tid + i * 256;                                           \
            int r = idx >> 3, c = idx & 7;                                     \
            cp16(ab + r * LROWB + c * 16, Ap + (size_t)r * K + c * 8);         \
        }                                                                      \
        _Pragma("unroll")                                                      \
        for (int i = 0; i < 4; i++) {                                          \
            int idx = tid + i * 256;                                           \
            int r = idx >> 3, c = idx & 7;                                     \
            cp16(bb + r * LROWB + c * 16, Wp + (size_t)r * K + c * 8);         \
        }                                                                      \
        cp_commit();                                                           \
    };                                                                         \
    float acc[2][8][4];                                                        \
    _Pragma("unroll")                                                          \
    for (int mi = 0; mi < 2; mi++)                                             \
        _Pragma("unroll")                                                      \
        for (int ni = 0; ni < 8; ni++)                                         \
            _Pragma("unroll")                                                  \
            for (int c = 0; c < 4; c++) acc[mi][ni][c] = 0.f;                  \
    load_stage(0, 0);                                                          \
    load_stage(1, 1);                                                          \
    for (int k = 0; k < num_k; k++) {                                          \
        cp_wait<NSTG - 2>();                                                   \
        __syncthreads();                                                       \
        int kn = k + 2;                                                        \
        if (kn < num_k) load_stage(kn, kn % NSTG); else cp_commit();           \
        uint32_t ab = sb + (k % NSTG) * STG_B + aoff;                          \
        uint32_t bb = sb + SOFF_B + (k % NSTG) * STG_B + boff;                 \
        _Pragma("unroll")                                                      \
        for (int ks = 0; ks < 4; ks++) {                                       \
            const uint32_t koff = ks * 32;                                     \
            uint32_t af[2][4], bf[4][4];                                       \
            ldmx4(af[0][0], af[0][1], af[0][2], af[0][3], ab + koff);          \
            ldmx4(af[1][0], af[1][1], af[1][2], af[1][3],                      \
                  ab + 16 * LROWB + koff);                                     \
            _Pragma("unroll")                                                  \
            for (int nj = 0; nj < 4; nj++)                                     \
                ldmx4(bf[nj][0], bf[nj][1], bf[nj][2], bf[nj][3],              \
                      bb + nj * 16 * LROWB + koff);                            \
            _Pragma("unroll")                                                  \
            for (int mi = 0; mi < 2; mi++)                                     \
                _Pragma("unroll")                                              \
                for (int ni = 0; ni < 8; ni++) {                               \
                    const uint32_t b0 = bf[ni >> 1][(ni & 1) * 2];             \
                    const uint32_t b1 = bf[ni >> 1][(ni & 1) * 2 + 1];         \
                    mma_f16(acc[mi][ni][0], acc[mi][ni][1],                    \
                            acc[mi][ni][2], acc[mi][ni][3],                    \
                            af[mi][0], af[mi][1], af[mi][2], af[mi][3],        \
                            b0, b1);                                           \
                }                                                              \
        }                                                                      \
    }

// ---------------------------------------------------------------------------
// Plain GEMM: C = A @ W^T (fp16 out). blockIdx.z selects W0/C0 vs W1/C1.
// ---------------------------------------------------------------------------
__global__ void __launch_bounds__(256, 2)
gemm_f16(const __half* __restrict__ A,
         const __half* __restrict__ W0, const __half* __restrict__ W1,
         __half* __restrict__ C0, __half* __restrict__ C1,
         int N, int K) {
    extern __shared__ __align__(16) char smem[];
    const uint32_t sb = s2u(smem);
    const __half* __restrict__ W = (blockIdx.z == 0) ? W0 : W1;
    __half* __restrict__ C = (blockIdx.z == 0) ? C0 : C1;

    GEMM_PROLOGUE_AND_MAINLOOP

    #pragma unroll
    for (int mi = 0; mi < 2; mi++)
        #pragma unroll
        for (int ni = 0; ni < 8; ni++) {
            int row = bm + wm + mi * 16 + g;
            int col = bn + wn + ni * 8 + tg * 2;
            *(__half2*)(C + (size_t)row * N + col) =
                __floats2half2_rn(acc[mi][ni][0], acc[mi][ni][1]);
            *(__half2*)(C + (size_t)(row + 8) * N + col) =
                __floats2half2_rn(acc[mi][ni][2], acc[mi][ni][3]);
        }
}

// ---------------------------------------------------------------------------
// Fused k/v GEMM. z==0: k-mode -> NO store; reduce sum(k^2), sum(x*k) per row
// (xh tile staged to smem). z==1: v-mode -> store vh AND reduce sum(v^2).
// ---------------------------------------------------------------------------
__global__ void __launch_bounds__(256, 2)
gemm_kv(const __half* __restrict__ A,
        const __half* __restrict__ W0, const __half* __restrict__ W1,
        __half* __restrict__ Cv, const __half* __restrict__ xh,
        float* __restrict__ pk2, float* __restrict__ pxk,
        float* __restrict__ pv2, int N, int K) {
    extern __shared__ __align__(16) char smem[];
    const uint32_t sb = s2u(smem);
    const bool kmode = (blockIdx.z == 0);
    const __half* __restrict__ W = kmode ? W0 : W1;

    GEMM_PROLOGUE_AND_MAINLOOP

    __syncthreads();                       // mainloop smem now reusable
    float* sred = (float*)(smem + 40960);  // s_k2[128] + s_xk[128] (or s_v2)
    if (tid < 128) { sred[tid] = 0.f; sred[128 + tid] = 0.f; }

    if (kmode) {
        // stage xh tile [128 rows x 128 cols] fp16, row stride 272 B
        const __half* Xb = xh + (size_t)bm * DDIM + bn;
        #pragma unroll
        for (int i = 0; i < 8; i++) {
            int idx = tid + i * 256;       // 2048 uint4
            int r = idx >> 4, c = idx & 15;
            *(uint4*)(smem + r * 272 + c * 16) =
                *(const uint4*)(Xb + (size_t)r * DDIM + c * 8);
        }
        __syncthreads();

        #pragma unroll
        for (int mi = 0; mi < 2; mi++) {
            int r0 = wm + mi * 16 + g;     // local rows
            int r1 = r0 + 8;
            float k20 = 0.f, k21 = 0.f, xk0 = 0.f, xk1 = 0.f;
            #pragma unroll
            for (int ni = 0; ni < 8; ni++) {
                int col = wn + ni * 8 + tg * 2;
                float2 fx0 = __half22float2(
                    *(const __half2*)(smem + r0 * 272 + col * 2));
                float2 fx1 = __half22float2(
                    *(const __half2*)(smem + r1 * 272 + col * 2));
                float c0 = acc[mi][ni][0], c1 = acc[mi][ni][1];
                float c2 = acc[mi][ni][2], c3 = acc[mi][ni][3];
                k20 += c0 * c0 + c1 * c1;
                k21 += c2 * c2 + c3 * c3;
                xk0 += fx0.x * c0 + fx0.y * c1;
                xk1 += fx1.x * c2 + fx1.y * c3;
            }
            #pragma unroll
            for (int off = 1; off < 4; off <<= 1) {   // quad reduce over tg
                k20 += __shfl_xor_sync(0xffffffffu, k20, off);
                k21 += __shfl_xor_sync(0xffffffffu, k21, off);
                xk0 += __shfl_xor_sync(0xffffffffu, xk0, off);
                xk1 += __shfl_xor_sync(0xffffffffu, xk1, off);
            }
            if (tg == 0) {
                atomicAdd(&sred[r0], k20);
                atomicAdd(&sred[r1], k21);
                atomicAdd(&sred[128 + r0], xk0);
                atomicAdd(&sred[128 + r1], xk1);
            }
        }
        __syncthreads();
        if (tid < 128) {
            pk2[(size_t)blockIdx.x * BT + bm + tid] = sred[tid];
            pxk[(size_t)blockIdx.x * BT + bm + tid] = sred[128 + tid];
        }
    } else {
        __syncthreads();
        #pragma unroll
        for (int mi = 0; mi < 2; mi++) {
            int r0 = wm + mi * 16 + g;
            int r1 = r0 + 8;
            float v20 = 0.f, v21 = 0.f;
            #pragma unroll
            for (int ni = 0; ni < 8; ni++) {
                int row = bm + r0;
                int col = bn + wn + ni * 8 + tg * 2;
                float c0 = acc[mi][ni][0], c1 = acc[mi][ni][1];
                float c2 = acc[mi][ni][2], c3 = acc[mi][ni][3];
                *(__half2*)(Cv + (size_t)row * N + col) =
                    __floats2half2_rn(c0, c1);
                *(__half2*)(Cv + (size_t)(row + 8) * N + col) =
                    __floats2half2_rn(c2, c3);
                v20 += c0 * c0 + c1 * c1;
                v21 += c2 * c2 + c3 * c3;
            }
            #pragma unroll
            for (int off = 1; off < 4; off <<= 1) {
                v20 += __shfl_xor_sync(0xffffffffu, v20, off);
                v21 += __shfl_xor_sync(0xffffffffu, v21, off);
            }
            if (tg == 0) {
                atomicAdd(&sred[r0], v20);
                atomicAdd(&sred[r1], v21);
            }
        }
        __syncthreads();
        if (tid < 128)
            pv2[(size_t)blockIdx.x * BT + bm + tid] = sred[tid];
    }
}

// ---------------------------------------------------------------------------
// Fused prep: one launch covering
//   blocks [0, BT)            : x -> fp16 + per-token sum(x^2)
//   blocks [BT, BT+768)       : 3 weight tensors fp32 -> fp16 (grid-stride)
//   blocks [BT+768, BT+1280)  : combine W_mix -> wch fp16 (grid-stride)
// ---------------------------------------------------------------------------
__global__ void __launch_bounds__(128)
prep(const float* __restrict__ x, __half* __restrict__ xh,
     float* __restrict__ sxx,
     const float* __restrict__ W_in, __half* __restrict__ winh,
     const float* __restrict__ W_k,  __half* __restrict__ wkh,
     const float* __restrict__ W_v,  __half* __restrict__ wvh,
     const float* __restrict__ wmix, __half* __restrict__ wc) {
    int b = blockIdx.x;
    if (b < BT) {
        int t = b;
        const float4* xp = (const float4*)(x + (size_t)t * DDIM);
        __half2* hp = (__half2*)(xh + (size_t)t * DDIM);
        float s = 0.f;
        #pragma unroll
        for (int r = 0; r < 4; r++) {
            int i = threadIdx.x + r * 128;
            float4 v = xp[i];
            s += v.x * v.x + v.y * v.y + v.z * v.z + v.w * v.w;
            hp[i * 2]     = __floats2half2_rn(v.x, v.y);
            hp[i * 2 + 1] = __floats2half2_rn(v.z, v.w);
        }
        #pragma unroll
        for (int off = 16; off > 0; off >>= 1)
            s += __shfl_down_sync(0xffffffffu, s, off);
        __shared__ float sh[4];
        int warp = threadIdx.x >> 5, lane = threadIdx.x & 31;
        if (lane == 0) sh[warp] = s;
        __syncthreads();
        if (threadIdx.x == 0)
            sxx[t] = sh[0] + sh[1] + sh[2] + sh[3];
        return;
    }
    b -= BT;
    if (b < 768) {
        const int n4 = DBDIM * DDIM / 4;   // 262144
        for (int i = b * 128 + threadIdx.x; i < 3 * n4; i += 768 * 128) {
            int seg = i / n4, j = i - seg * n4;
            const float* sp = (seg == 0) ? W_in : (seg == 1) ? W_k : W_v;
            __half* dp      = (seg == 0) ? winh : (seg == 1) ? wkh : wvh;
            float4 v = ((const float4*)sp)[j];
            __half2* p = (__half2*)dp + (size_t)j * 2;
            p[0] = __floats2half2_rn(v.x, v.y);
            p[1] = __floats2half2_rn(v.z, v.w);
        }
        return;
    }
    b -= 768;
    const float c2 = 1.0f / 6.0f, c3 = 1.0f / 9.0f, c4 = 1.0f / 12.0f;
    for (int idx = b * 128 + threadIdx.x; idx < DBDIM * DBDIM;
         idx += 512 * 128) {
        float w2 = wmix[0 * DBDIM * DBDIM + idx];
        float w3 = wmix[1 * DBDIM * DBDIM + idx];
        float w4 = wmix[2 * DBDIM * DBDIM + idx];
        wc[idx]                     = __float2half_rn(w2 * c2 + w3 * c3 + w4 * c4);
        wc[DBDIM * DBDIM + idx]     = __float2half_rn(w3 * c3 + w4 * c4);
        wc[2 * DBDIM * DBDIM + idx] = __float2half_rn(w4 * c4);
    }
}

// ---------------------------------------------------------------------------
// Gather y[t] = zm0[t] + m1*zm0[t-1] + m2*zm1[t-2] + m3*zm2[t-3]  (fp16)
// ---------------------------------------------------------------------------
__global__ void __launch_bounds__(128)
build_y(const __half* __restrict__ zm, const int* __restrict__ doc,
        __half* __restrict__ y) {
    int t  = blockIdx.x;
    int tt = t & (TDIM - 1);
    int d0 = doc[t];
    bool m1 = (tt >= 1) && (doc[t - 1] == d0);
    bool m2 = (tt >= 2) && (doc[t - 2] == d0);
    bool m3 = (tt >= 3) && (doc[t - 3] == d0);

    const float2* p0 = (const float2*)(zm + (size_t)t * 1536);
    const float2* p1 = (const float2*)(zm + (size_t)(t - 1) * 1536);
    const float2* p2 = (const float2*)(zm + (size_t)(t - 2) * 1536 + 512);
    const float2* p3 = (const float2*)(zm + (size_t)(t - 3) * 1536 + 1024);

    int i = threadIdx.x;
    float2 r0 = p0[i];
    __half2* h0 = (__half2*)&r0;
    float2 lo = __half22float2(h0[0]);
    float2 hi = __half22float2(h0[1]);
    if (m1) {
        float2 q = p1[i]; __half2* h = (__half2*)&q;
        float2 a = __half22float2(h[0]), b = __half22float2(h[1]);
        lo.x += a.x; lo.y += a.y; hi.x += b.x; hi.y += b.y;
    }
    if (m2) {
        float2 q = p2[i]; __half2* h = (__half2*)&q;
        float2 a = __half22float2(h[0]), b = __half22float2(h[1]);
        lo.x += a.x; lo.y += a.y; hi.x += b.x; hi.y += b.y;
    }
    if (m3) {
        float2 q = p3[i]; __half2* h = (__half2*)&q;
        float2 a = __half22float2(h[0]), b = __half22float2(h[1]);
        lo.x += a.x; lo.y += a.y; hi.x += b.x; hi.y += b.y;
    }
    __half2* yp = (__half2*)(y + (size_t)t * DBDIM) + i * 2;
    yp[0] = __floats2half2_rn(lo.x, lo.y);
    yp[1] = __floats2half2_rn(hi.x, hi.y);
}

// ---------------------------------------------------------------------------
// Fused gate + depthwise causal conv (K=4) + SiLU.
// Warps 0-3 recompute scale[t-s] from the gate partials (16 col-blocks each,
// lanes 0-15 load + shfl-reduce); all threads load v rows; then
// out[t,d] = silu( sum_s mask_s * v[t-s,d]*scale[t-s]*cw[d,3-s] ).
// ---------------------------------------------------------------------------
__global__ void __launch_bounds__(256)
conv_silu(const __half* __restrict__ vh, const float* __restrict__ sxxA,
          const float* __restrict__ pk2, const float* __restrict__ pxk,
          const float* __restrict__ pv2, const int* __restrict__ doc,
          const float* __restrict__ cw, float* __restrict__ out) {
    int t  = blockIdx.x;
    int tt = t & (TDIM - 1);
    int d0 = doc[t];

    int  trow[4];
    bool msk[4];
    trow[0] = t; msk[0] = true;
    #pragma unroll
    for (int s = 1; s < 4; s++) {
        bool inb = (tt >= s) && (doc[t - s] == d0);
        msk[s]  = inb;
        trow[s] = inb ? (t - s) : t;
    }

    // v row loads (issued early; independent of the scale computation)
    int i = threadIdx.x;
    int d = i * 8;
    uint4 q0 = ((const uint4*)(vh + (size_t)trow[0] * DDIM))[i];
    uint4 q1 = ((const uint4*)(vh + (size_t)trow[1] * DDIM))[i];
    uint4 q2 = ((const uint4*)(vh + (size_t)trow[2] * DDIM))[i];
    uint4 q3 = ((const uint4*)(vh + (size_t)trow[3] * DDIM))[i];

    // warps 0-3: compute scale for trow[warp]
    __shared__ float ssc[4];
    int warp = threadIdx.x >> 5, lane = threadIdx.x & 31;
    if (warp < 4) {
        int tau = trow[warp];
        float a = 0.f, b = 0.f, c = 0.f;
        if (lane < 16) {
            a = pk2[(size_t)lane * BT + tau];
            b = pxk[(size_t)lane * BT + tau];
            c = pv2[(size_t)lane * BT + tau];
        }
        #pragma unroll
        for (int off = 8; off > 0; off >>= 1) {
            a += __shfl_down_sync(0xffffffffu, a, off);
            b += __shfl_down_sync(0xffffffffu, b, off);
            c += __shfl_down_sync(0xffffffffu, c, off);
        }
        if (lane == 0) {
            float sxx = sxxA[tau];
            const float invD = 1.0f / (float)DDIM;
            float gv = b * rsqrtf(sxx * invD + EPSV) * rsqrtf(a * invD + EPSV)
                         * rsqrtf((float)DDIM);
            float sg = (gv > 0.f) ? 1.f : ((gv < 0.f) ? -1.f : 0.f);
            float gl = sg * sqrtf(fmaxf(fabsf(gv), 1e-6f));
            float gate = 1.0f / (1.0f + expf(-gl));
            ssc[warp] = gate * rsqrtf(gate * gate * (c * invD) + EPSV);
        }
    }
    __syncthreads();
    float c0 = ssc[0];
    float c1 = msk[1] ? ssc[1] : 0.f;
    float c2 = msk[2] ? ssc[2] : 0.f;
    float c3 = msk[3] ? ssc[3] : 0.f;

    float f0[8], f1[8], f2[8], f3[8];
    {
        const __half2* h0 = (const __half2*)&q0;
        const __half2* h1 = (const __half2*)&q1;
        const __half2* h2 = (const __half2*)&q2;
        const __half2* h3 = (const __half2*)&q3;
        #pragma unroll
        for (int m = 0; m < 4; m++) {
            float2 a = __half22float2(h0[m]); f0[2*m] = a.x; f0[2*m+1] = a.y;
            float2 b = __half22float2(h1[m]); f1[2*m] = b.x; f1[2*m+1] = b.y;
            float2 c = __half22float2(h2[m]); f2[2*m] = c.x; f2[2*m+1] = c.y;
            float2 e = __half22float2(h3[m]); f3[2*m] = e.x; f3[2*m+1] = e.y;
        }
    }

    float o[8];
    #pragma unroll
    for (int j = 0; j < 8; j++) {
        float4 w = *(const float4*)(cw + (size_t)(d + j) * 4);  // taps [0..3]
        float res = f0[j] * c0 * w.w + f1[j] * c1 * w.z
                  + f2[j] * c2 * w.y + f3[j] * c3 * w.x;
        o[j] = res / (1.0f + expf(-res));   // SiLU
    }
    float4* op = (float4*)(out + (size_t)t * DDIM + d);
    op[0] = make_float4(o[0], o[1], o[2], o[3]);
    op[1] = make_float4(o[4], o[5], o[6], o[7]);
}

// ---------------------------------------------------------------------------
extern "C" void kernel_launch(void* const* d_in, const int* in_sizes, int n_in,
                              void* d_out, int out_size) {
    const float* x      = (const float*)d_in[0];
    const int*   doc    = (const int*)  d_in[1];
    const float* W_in   = (const float*)d_in[2];
    const float* W_mix  = (const float*)d_in[3];
    const float* W_k    = (const float*)d_in[4];
    const float* W_v    = (const float*)d_in[5];
    const float* conv_w = (const float*)d_in[6];
    float* out = (float*)d_out;

    __half *xh, *winh, *wkh, *wvh, *wch, *zh, *zm, *yh, *vh;
    float *sxx, *pk2, *pxk, *pv2;
    cudaGetSymbolAddress((void**)&xh,    g_xh);
    cudaGetSymbolAddress((void**)&winh,  g_winh);
    cudaGetSymbolAddress((void**)&wkh,   g_wkh);
    cudaGetSymbolAddress((void**)&wvh,   g_wvh);
    cudaGetSymbolAddress((void**)&wch,   g_wch);
    cudaGetSymbolAddress((void**)&zh,    g_zh);
    cudaGetSymbolAddress((void**)&zm,    g_zm);
    cudaGetSymbolAddress((void**)&yh,    g_yh);
    cudaGetSymbolAddress((void**)&vh,    g_vh);
    cudaGetSymbolAddress((void**)&sxx,   g_sxx);
    cudaGetSymbolAddress((void**)&pk2,   g_pk2);
    cudaGetSymbolAddress((void**)&pxk,   g_pxk);
    cudaGetSymbolAddress((void**)&pv2,   g_pv2);

    cudaFuncSetAttribute(gemm_f16,
                         cudaFuncAttributeMaxDynamicSharedMemorySize, GEMM_SMEM);
    cudaFuncSetAttribute(gemm_kv,
                         cudaFuncAttributeMaxDynamicSharedMemorySize, GEMM_SMEM);

    // 0) fused prep: x->fp16(+sum x^2), 3 weight conversions, wmix combine
    prep<<<BT + 768 + 512, 128>>>(x, xh, sxx, W_in, winh, W_k, wkh,
                                  W_v, wvh, W_mix, wch);

    // 1) z = xh @ winh^T -> fp16
    gemm_f16<<<dim3(DBDIM / TBN, BT / TBM, 1), 256, GEMM_SMEM>>>(
        xh, winh, winh, zh, zh, DBDIM, DDIM);

    // 2) zm = zh @ wch^T -> fp16
    gemm_f16<<<dim3(3 * DBDIM / TBN, BT / TBM, 1), 256, GEMM_SMEM>>>(
        zh, wch, wch, zm, zm, 3 * DBDIM, DBDIM);

    // 3) y gather -> fp16
    build_y<<<BT, 128>>>(zm, doc, yh);

    // 4) fused k/v: z=0 -> gate partials (k never stored); z=1 -> vh + v^2
    gemm_kv<<<dim3(DDIM / TBN, BT / TBM, 2), 256, GEMM_SMEM>>>(
        yh, wkh, wvh, vh, xh, pk2, pxk, pv2, DDIM, DBDIM);

    // 5) fused gate recompute + depthwise causal conv + SiLU -> output
    conv_silu<<<BT, 256>>>(vh, sxx, pk2, pxk, pv2, doc, conv_w, out);
}

// round 17
// speedup vs baseline: 1.0178x; 1.0178x over previous
#include <cuda_runtime.h>
#include <cuda_fp16.h>
#include <cstdint>
#include <math.h>

// Problem constants
#define BDIM   4
#define TDIM   4096
#define DDIM   2048
#define DBDIM  512
#define BT     (BDIM * TDIM)   // 16384 tokens
#define EPSV   1e-6f

// ---------------- scratch (static device globals; no runtime allocation) ----
__device__ __half g_xh  [(size_t)BT * DDIM];         // fp16 x
__device__ __half g_winh[(size_t)DBDIM * DDIM];      // fp16 W_in
__device__ __half g_wkh [(size_t)DDIM * DBDIM];      // fp16 W_k
__device__ __half g_wvh [(size_t)DDIM * DBDIM];      // fp16 W_v
__device__ __half g_wch [(size_t)3 * DBDIM * DBDIM]; // fp16 combined mix W [1536,512]
__device__ __half g_zh  [(size_t)BT * DBDIM];        // fp16 bottleneck proj
__device__ __half g_zm  [(size_t)BT * 3 * DBDIM];    // fp16 z @ [M0|M1|M2]
__device__ __half g_yh  [(size_t)BT * DBDIM];        // fp16 mixed
__device__ __half g_vh  [(size_t)BT * DDIM];         // fp16 value proj
__device__ float  g_sxx [(size_t)BT];                // per-token sum x^2
__device__ float  g_pk2 [(size_t)16 * BT];           // per-colblock partial sum k^2
__device__ float  g_pxk [(size_t)16 * BT];           // per-colblock partial sum x*k
__device__ float  g_pv2 [(size_t)16 * BT];           // per-colblock partial sum v^2
__device__ float  g_scale[(size_t)BT];               // per-token gate*rms scale

// ---------------------------------------------------------------------------
// helpers
// ---------------------------------------------------------------------------
__device__ __forceinline__ uint32_t s2u(const void* p) {
    uint32_t a;
    asm("{ .reg .u64 t; cvta.to.shared.u64 t, %1; cvt.u32.u64 %0, t; }"
        : "=r"(a) : "l"(p));
    return a;
}

__device__ __forceinline__ void cp16(uint32_t dst, const void* src) {
    asm volatile("cp.async.cg.shared.global [%0], [%1], 16;" :: "r"(dst), "l"(src));
}
__device__ __forceinline__ void cp_commit() {
    asm volatile("cp.async.commit_group;" ::: "memory");
}
template<int N> __device__ __forceinline__ void cp_wait() {
    asm volatile("cp.async.wait_group %0;" :: "n"(N) : "memory");
}

__device__ __forceinline__ void ldmx4(uint32_t& r0, uint32_t& r1,
                                      uint32_t& r2, uint32_t& r3, uint32_t addr) {
    asm volatile("ldmatrix.sync.aligned.m8n8.x4.shared.b16 {%0,%1,%2,%3}, [%4];"
        : "=r"(r0), "=r"(r1), "=r"(r2), "=r"(r3) : "r"(addr));
}

// mma.sync m16n8k16 fp16 inputs, fp32 accumulate
__device__ __forceinline__ void mma_f16(float& c0, float& c1, float& c2, float& c3,
                                        uint32_t a0, uint32_t a1, uint32_t a2,
                                        uint32_t a3, uint32_t b0, uint32_t b1) {
    asm volatile(
        "mma.sync.aligned.m16n8k16.row.col.f32.f16.f16.f32 "
        "{%0,%1,%2,%3}, {%4,%5,%6,%7}, {%8,%9}, {%0,%1,%2,%3};"
        : "+f"(c0), "+f"(c1), "+f"(c2), "+f"(c3)
        : "r"(a0), "r"(a1), "r"(a2), "r"(a3), "r"(b0), "r"(b1));
}

// ---------------------------------------------------------------------------
// GEMM config (champion): 128x128x64 tile, 8 warps (4m x 2n), warp tile
// 32x64, 3-stage cp.async, 2 CTAs/SM, ldmatrix.x4 frags, 144B padded rows.
// ---------------------------------------------------------------------------
#define TBM    128
#define TBN    128
#define TBK    64
#define NSTG   3
#define LROWB  144
#define STG_B  (128 * LROWB)            // 18432 B
#define SOFF_B (NSTG * STG_B)
#define GEMM_SMEM (2 * NSTG * STG_B)    // 110592 B

#define GEMM_PROLOGUE_AND_MAINLOOP                                             \
    const int tid  = threadIdx.x;                                              \
    const int lane = tid & 31;                                                 \
    const int wid  = tid >> 5;                                                 \
    const int wm   = (wid & 3) * 32;                                           \
    const int wn   = (wid >> 2) * 64;                                          \
    const int g    = lane >> 2;                                                \
    const int tg   = lane & 3;                                                 \
    const uint32_t aoff = (uint32_t)(wm + (lane & 7) + ((lane >> 3) & 1) * 8)  \
                          * LROWB + ((lane >> 4) & 1) * 16;                    \
    const uint32_t boff = (uint32_t)(wn + (lane & 7) + ((lane >> 4) & 1) * 8)  \
                          * LROWB + ((lane >> 3) & 1) * 16;                    \
    const int bm = blockIdx.y * TBM;                                           \
    const int bn = blockIdx.x * TBN;                                           \
    const int num_k = K / TBK;                                                 \
    const __half* Abase = A + (size_t)bm * K;                                  \
    const __half* Wbase = W + (size_t)bn * K;                                  \
    auto load_stage = [&](int ks, int buf) {                                   \
        const __half* Ap = Abase + ks * TBK;                                   \
        const __half* Wp = Wbase + ks * TBK;                                   \
        uint32_t ab = sb + buf * STG_B;                                        \
        uint32_t bb = sb + SOFF_B + buf * STG_B;                               \
        _Pragma("unroll")                                                      \
        for (int i = 0; i < 4; i++) {                                          \
            int idx = tid + i * 256;                                           \
            int r = idx >> 3, c = idx & 7;                                     \
            cp16(ab + r * LROWB + c * 16, Ap + (size_t)r * K + c * 8);         \
        }                                                                      \
        _Pragma("unroll")                                                      \
        for (int i = 0; i < 4; i++) {                                          \
            int idx = tid + i * 256;                                           \
            int r = idx >> 3, c = idx & 7;                                     \
            cp16(bb + r * LROWB + c * 16, Wp + (size_t)r * K + c * 8);         \
        }                                                                      \
        cp_commit();                                                           \
    };                                                                         \
    float acc[2][8][4];                                                        \
    _Pragma("unroll")                                                          \
    for (int mi = 0; mi < 2; mi++)                                             \
        _Pragma("unroll")                                                      \
        for (int ni = 0; ni < 8; ni++)                                         \
            _Pragma("unroll")                                                  \
            for (int c = 0; c < 4; c++) acc[mi][ni][c] = 0.f;                  \
    load_stage(0, 0);                                                          \
    load_stage(1, 1);                                                          \
    for (int k = 0; k < num_k; k++) {                                          \
        cp_wait<NSTG - 2>();                                                   \
        __syncthreads();                                                       \
        int kn = k + 2;                                                        \
        if (kn < num_k) load_stage(kn, kn % NSTG); else cp_commit();           \
        uint32_t ab = sb + (k % NSTG) * STG_B + aoff;                          \
        uint32_t bb = sb + SOFF_B + (k % NSTG) * STG_B + boff;                 \
        _Pragma("unroll")                                                      \
        for (int ks = 0; ks < 4; ks++) {                                       \
            const uint32_t koff = ks * 32;                                     \
            uint32_t af[2][4], bf[4][4];                                       \
            ldmx4(af[0][0], af[0][1], af[0][2], af[0][3], ab + koff);          \
            ldmx4(af[1][0], af[1][1], af[1][2], af[1][3],                      \
                  ab + 16 * LROWB + koff);                                     \
            _Pragma("unroll")                                                  \
            for (int nj = 0; nj < 4; nj++)                                     \
                ldmx4(bf[nj][0], bf[nj][1], bf[nj][2], bf[nj][3],              \
                      bb + nj * 16 * LROWB + koff);                            \
            _Pragma("unroll")                                                  \
            for (int mi = 0; mi < 2; mi++)                                     \
                _Pragma("unroll")                                              \
                for (int ni = 0; ni < 8; ni++) {                               \
                    const uint32_t b0 = bf[ni >> 1][(ni & 1) * 2];             \
                    const uint32_t b1 = bf[ni >> 1][(ni & 1) * 2 + 1];         \
                    mma_f16(acc[mi][ni][0], acc[mi][ni][1],                    \
                            acc[mi][ni][2], acc[mi][ni][3],                    \
                            af[mi][0], af[mi][1], af[mi][2], af[mi][3],        \
                            b0, b1);                                           \
                }                                                              \
        }                                                                      \
    }

// ---------------------------------------------------------------------------
// Plain GEMM: C = A @ W^T (fp16 out). blockIdx.z selects W0/C0 vs W1/C1.
// ---------------------------------------------------------------------------
__global__ void __launch_bounds__(256, 2)
gemm_f16(const __half* __restrict__ A,
         const __half* __restrict__ W0, const __half* __restrict__ W1,
         __half* __restrict__ C0, __half* __restrict__ C1,
         int N, int K) {
    extern __shared__ __align__(16) char smem[];
    const uint32_t sb = s2u(smem);
    const __half* __restrict__ W = (blockIdx.z == 0) ? W0 : W1;
    __half* __restrict__ C = (blockIdx.z == 0) ? C0 : C1;

    GEMM_PROLOGUE_AND_MAINLOOP

    #pragma unroll
    for (int mi = 0; mi < 2; mi++)
        #pragma unroll
        for (int ni = 0; ni < 8; ni++) {
            int row = bm + wm + mi * 16 + g;
            int col = bn + wn + ni * 8 + tg * 2;
            *(__half2*)(C + (size_t)row * N + col) =
                __floats2half2_rn(acc[mi][ni][0], acc[mi][ni][1]);
            *(__half2*)(C + (size_t)(row + 8) * N + col) =
                __floats2half2_rn(acc[mi][ni][2], acc[mi][ni][3]);
        }
}

// ---------------------------------------------------------------------------
// Fused k/v GEMM. z==0: k-mode -> NO store; reduce sum(k^2), sum(x*k) per row
// (xh tile staged to smem). z==1: v-mode -> store vh AND reduce sum(v^2).
// ---------------------------------------------------------------------------
__global__ void __launch_bounds__(256, 2)
gemm_kv(const __half* __restrict__ A,
        const __half* __restrict__ W0, const __half* __restrict__ W1,
        __half* __restrict__ Cv, const __half* __restrict__ xh,
        float* __restrict__ pk2, float* __restrict__ pxk,
        float* __restrict__ pv2, int N, int K) {
    extern __shared__ __align__(16) char smem[];
    const uint32_t sb = s2u(smem);
    const bool kmode = (blockIdx.z == 0);
    const __half* __restrict__ W = kmode ? W0 : W1;

    GEMM_PROLOGUE_AND_MAINLOOP

    __syncthreads();                       // mainloop smem now reusable
    float* sred = (float*)(smem + 40960);  // s_k2[128] + s_xk[128] (or s_v2)
    if (tid < 128) { sred[tid] = 0.f; sred[128 + tid] = 0.f; }

    if (kmode) {
        // stage xh tile [128 rows x 128 cols] fp16, row stride 272 B
        const __half* Xb = xh + (size_t)bm * DDIM + bn;
        #pragma unroll
        for (int i = 0; i < 8; i++) {
            int idx = tid + i * 256;       // 2048 uint4
            int r = idx >> 4, c = idx & 15;
            *(uint4*)(smem + r * 272 + c * 16) =
                *(const uint4*)(Xb + (size_t)r * DDIM + c * 8);
        }
        __syncthreads();

        #pragma unroll
        for (int mi = 0; mi < 2; mi++) {
            int r0 = wm + mi * 16 + g;     // local rows
            int r1 = r0 + 8;
            float k20 = 0.f, k21 = 0.f, xk0 = 0.f, xk1 = 0.f;
            #pragma unroll
            for (int ni = 0; ni < 8; ni++) {
                int col = wn + ni * 8 + tg * 2;
                float2 fx0 = __half22float2(
                    *(const __half2*)(smem + r0 * 272 + col * 2));
                float2 fx1 = __half22float2(
                    *(const __half2*)(smem + r1 * 272 + col * 2));
                float c0 = acc[mi][ni][0], c1 = acc[mi][ni][1];
                float c2 = acc[mi][ni][2], c3 = acc[mi][ni][3];
                k20 += c0 * c0 + c1 * c1;
                k21 += c2 * c2 + c3 * c3;
                xk0 += fx0.x * c0 + fx0.y * c1;
                xk1 += fx1.x * c2 + fx1.y * c3;
            }
            #pragma unroll
            for (int off = 1; off < 4; off <<= 1) {   // quad reduce over tg
                k20 += __shfl_xor_sync(0xffffffffu, k20, off);
                k21 += __shfl_xor_sync(0xffffffffu, k21, off);
                xk0 += __shfl_xor_sync(0xffffffffu, xk0, off);
                xk1 += __shfl_xor_sync(0xffffffffu, xk1, off);
            }
            if (tg == 0) {
                atomicAdd(&sred[r0], k20);
                atomicAdd(&sred[r1], k21);
                atomicAdd(&sred[128 + r0], xk0);
                atomicAdd(&sred[128 + r1], xk1);
            }
        }
        __syncthreads();
        if (tid < 128) {
            pk2[(size_t)blockIdx.x * BT + bm + tid] = sred[tid];
            pxk[(size_t)blockIdx.x * BT + bm + tid] = sred[128 + tid];
        }
    } else {
        __syncthreads();
        #pragma unroll
        for (int mi = 0; mi < 2; mi++) {
            int r0 = wm + mi * 16 + g;
            int r1 = r0 + 8;
            float v20 = 0.f, v21 = 0.f;
            #pragma unroll
            for (int ni = 0; ni < 8; ni++) {
                int row = bm + r0;
                int col = bn + wn + ni * 8 + tg * 2;
                float c0 = acc[mi][ni][0], c1 = acc[mi][ni][1];
                float c2 = acc[mi][ni][2], c3 = acc[mi][ni][3];
                *(__half2*)(Cv + (size_t)row * N + col) =
                    __floats2half2_rn(c0, c1);
                *(__half2*)(Cv + (size_t)(row + 8) * N + col) =
                    __floats2half2_rn(c2, c3);
                v20 += c0 * c0 + c1 * c1;
                v21 += c2 * c2 + c3 * c3;
            }
            #pragma unroll
            for (int off = 1; off < 4; off <<= 1) {
                v20 += __shfl_xor_sync(0xffffffffu, v20, off);
                v21 += __shfl_xor_sync(0xffffffffu, v21, off);
            }
            if (tg == 0) {
                atomicAdd(&sred[r0], v20);
                atomicAdd(&sred[r1], v21);
            }
        }
        __syncthreads();
        if (tid < 128)
            pv2[(size_t)blockIdx.x * BT + bm + tid] = sred[tid];
    }
}

// ---------------------------------------------------------------------------
// Fused prep: one launch covering
//   blocks [0, BT)            : x -> fp16 + per-token sum(x^2)
//   blocks [BT, BT+768)       : 3 weight tensors fp32 -> fp16 (grid-stride)
//   blocks [BT+768, BT+1280)  : combine W_mix -> wch fp16 (grid-stride)
// ---------------------------------------------------------------------------
__global__ void __launch_bounds__(128)
prep(const float* __restrict__ x, __half* __restrict__ xh,
     float* __restrict__ sxx,
     const float* __restrict__ W_in, __half* __restrict__ winh,
     const float* __restrict__ W_k,  __half* __restrict__ wkh,
     const float* __restrict__ W_v,  __half* __restrict__ wvh,
     const float* __restrict__ wmix, __half* __restrict__ wc) {
    int b = blockIdx.x;
    if (b < BT) {
        int t = b;
        const float4* xp = (const float4*)(x + (size_t)t * DDIM);
        __half2* hp = (__half2*)(xh + (size_t)t * DDIM);
        float s = 0.f;
        #pragma unroll
        for (int r = 0; r < 4; r++) {
            int i = threadIdx.x + r * 128;
            float4 v = xp[i];
            s += v.x * v.x + v.y * v.y + v.z * v.z + v.w * v.w;
            hp[i * 2]     = __floats2half2_rn(v.x, v.y);
            hp[i * 2 + 1] = __floats2half2_rn(v.z, v.w);
        }
        #pragma unroll
        for (int off = 16; off > 0; off >>= 1)
            s += __shfl_down_sync(0xffffffffu, s, off);
        __shared__ float sh[4];
        int warp = threadIdx.x >> 5, lane = threadIdx.x & 31;
        if (lane == 0) sh[warp] = s;
        __syncthreads();
        if (threadIdx.x == 0)
            sxx[t] = sh[0] + sh[1] + sh[2] + sh[3];
        return;
    }
    b -= BT;
    if (b < 768) {
        const int n4 = DBDIM * DDIM / 4;   // 262144
        for (int i = b * 128 + threadIdx.x; i < 3 * n4; i += 768 * 128) {
            int seg = i / n4, j = i - seg * n4;
            const float* sp = (seg == 0) ? W_in : (seg == 1) ? W_k : W_v;
            __half* dp      = (seg == 0) ? winh : (seg == 1) ? wkh : wvh;
            float4 v = ((const float4*)sp)[j];
            __half2* p = (__half2*)dp + (size_t)j * 2;
            p[0] = __floats2half2_rn(v.x, v.y);
            p[1] = __floats2half2_rn(v.z, v.w);
        }
        return;
    }
    b -= 768;
    const float c2 = 1.0f / 6.0f, c3 = 1.0f / 9.0f, c4 = 1.0f / 12.0f;
    for (int idx = b * 128 + threadIdx.x; idx < DBDIM * DBDIM;
         idx += 512 * 128) {
        float w2 = wmix[0 * DBDIM * DBDIM + idx];
        float w3 = wmix[1 * DBDIM * DBDIM + idx];
        float w4 = wmix[2 * DBDIM * DBDIM + idx];
        wc[idx]                     = __float2half_rn(w2 * c2 + w3 * c3 + w4 * c4);
        wc[DBDIM * DBDIM + idx]     = __float2half_rn(w3 * c3 + w4 * c4);
        wc[2 * DBDIM * DBDIM + idx] = __float2half_rn(w4 * c4);
    }
}

// ---------------------------------------------------------------------------
// Gather y[t] = zm0[t] + m1*zm0[t-1] + m2*zm1[t-2] + m3*zm2[t-3]  (fp16)
// ---------------------------------------------------------------------------
__global__ void __launch_bounds__(128)
build_y(const __half* __restrict__ zm, const int* __restrict__ doc,
        __half* __restrict__ y) {
    int t  = blockIdx.x;
    int tt = t & (TDIM - 1);
    int d0 = doc[t];
    bool m1 = (tt >= 1) && (doc[t - 1] == d0);
    bool m2 = (tt >= 2) && (doc[t - 2] == d0);
    bool m3 = (tt >= 3) && (doc[t - 3] == d0);

    const float2* p0 = (const float2*)(zm + (size_t)t * 1536);
    const float2* p1 = (const float2*)(zm + (size_t)(t - 1) * 1536);
    const float2* p2 = (const float2*)(zm + (size_t)(t - 2) * 1536 + 512);
    const float2* p3 = (const float2*)(zm + (size_t)(t - 3) * 1536 + 1024);

    int i = threadIdx.x;
    float2 r0 = p0[i];
    __half2* h0 = (__half2*)&r0;
    float2 lo = __half22float2(h0[0]);
    float2 hi = __half22float2(h0[1]);
    if (m1) {
        float2 q = p1[i]; __half2* h = (__half2*)&q;
        float2 a = __half22float2(h[0]), b = __half22float2(h[1]);
        lo.x += a.x; lo.y += a.y; hi.x += b.x; hi.y += b.y;
    }
    if (m2) {
        float2 q = p2[i]; __half2* h = (__half2*)&q;
        float2 a = __half22float2(h[0]), b = __half22float2(h[1]);
        lo.x += a.x; lo.y += a.y; hi.x += b.x; hi.y += b.y;
    }
    if (m3) {
        float2 q = p3[i]; __half2* h = (__half2*)&q;
        float2 a = __half22float2(h[0]), b = __half22float2(h[1]);
        lo.x += a.x; lo.y += a.y; hi.x += b.x; hi.y += b.y;
    }
    __half2* yp = (__half2*)(y + (size_t)t * DBDIM) + i * 2;
    yp[0] = __floats2half2_rn(lo.x, lo.y);
    yp[1] = __floats2half2_rn(hi.x, hi.y);
}

// ---------------------------------------------------------------------------
// Combine partials -> per-token scale (16 column blocks)
// ---------------------------------------------------------------------------
__global__ void __launch_bounds__(256)
gate_combine(const float* __restrict__ sxxA, const float* __restrict__ pk2,
             const float* __restrict__ pxk, const float* __restrict__ pv2,
             float* __restrict__ scale) {
    int t = blockIdx.x * 256 + threadIdx.x;
    float skk = 0.f, sxk = 0.f, svv = 0.f;
    #pragma unroll
    for (int j = 0; j < 16; j++) {
        skk += pk2[(size_t)j * BT + t];
        sxk += pxk[(size_t)j * BT + t];
        svv += pv2[(size_t)j * BT + t];
    }
    float sxx = sxxA[t];
    const float invD = 1.0f / (float)DDIM;
    float g = sxk * rsqrtf(sxx * invD + EPSV) * rsqrtf(skk * invD + EPSV)
                  * rsqrtf((float)DDIM);
    float sg = (g > 0.f) ? 1.f : ((g < 0.f) ? -1.f : 0.f);
    float gl = sg * sqrtf(fmaxf(fabsf(g), 1e-6f));
    float gate = 1.0f / (1.0f + expf(-gl));
    scale[t] = gate * rsqrtf(gate * gate * (svv * invD) + EPSV);
}

// ---------------------------------------------------------------------------
// Depthwise causal conv (K=4) + SiLU; normed[t] = v[t]*scale[t] on the fly.
// ---------------------------------------------------------------------------
__global__ void __launch_bounds__(256)
conv_silu(const __half* __restrict__ vh, const float* __restrict__ scale,
          const int* __restrict__ doc, const float* __restrict__ cw,
          float* __restrict__ out) {
    int t  = blockIdx.x;
    int tt = t & (TDIM - 1);
    int d0 = doc[t];

    float c0 = scale[t], c1 = 0.f, c2 = 0.f, c3 = 0.f;
    int r1 = t, r2 = t, r3 = t;
    if (tt >= 1 && doc[t - 1] == d0) { c1 = scale[t - 1]; r1 = t - 1; }
    if (tt >= 2 && doc[t - 2] == d0) { c2 = scale[t - 2]; r2 = t - 2; }
    if (tt >= 3 && doc[t - 3] == d0) { c3 = scale[t - 3]; r3 = t - 3; }

    int i = threadIdx.x;
    int d = i * 8;
    uint4 q0 = ((const uint4*)(vh + (size_t)t  * DDIM))[i];
    uint4 q1 = ((const uint4*)(vh + (size_t)r1 * DDIM))[i];
    uint4 q2 = ((const uint4*)(vh + (size_t)r2 * DDIM))[i];
    uint4 q3 = ((const uint4*)(vh + (size_t)r3 * DDIM))[i];

    float f0[8], f1[8], f2[8], f3[8];
    {
        const __half2* h0 = (const __half2*)&q0;
        const __half2* h1 = (const __half2*)&q1;
        const __half2* h2 = (const __half2*)&q2;
        const __half2* h3 = (const __half2*)&q3;
        #pragma unroll
        for (int m = 0; m < 4; m++) {
            float2 a = __half22float2(h0[m]); f0[2*m] = a.x; f0[2*m+1] = a.y;
            float2 b = __half22float2(h1[m]); f1[2*m] = b.x; f1[2*m+1] = b.y;
            float2 c = __half22float2(h2[m]); f2[2*m] = c.x; f2[2*m+1] = c.y;
            float2 e = __half22float2(h3[m]); f3[2*m] = e.x; f3[2*m+1] = e.y;
        }
    }

    float o[8];
    #pragma unroll
    for (int j = 0; j < 8; j++) {
        float4 w = *(const float4*)(cw + (size_t)(d + j) * 4);
        float res = f0[j] * c0 * w.w + f1[j] * c1 * w.z
                  + f2[j] * c2 * w.y + f3[j] * c3 * w.x;
        o[j] = res / (1.0f + expf(-res));
    }
    float4* op = (float4*)(out + (size_t)t * DDIM + d);
    op[0] = make_float4(o[0], o[1], o[2], o[3]);
    op[1] = make_float4(o[4], o[5], o[6], o[7]);
}

// ---------------------------------------------------------------------------
extern "C" void kernel_launch(void* const* d_in, const int* in_sizes, int n_in,
                              void* d_out, int out_size) {
    const float* x      = (const float*)d_in[0];
    const int*   doc    = (const int*)  d_in[1];
    const float* W_in   = (const float*)d_in[2];
    const float* W_mix  = (const float*)d_in[3];
    const float* W_k    = (const float*)d_in[4];
    const float* W_v    = (const float*)d_in[5];
    const float* conv_w = (const float*)d_in[6];
    float* out = (float*)d_out;

    __half *xh, *winh, *wkh, *wvh, *wch, *zh, *zm, *yh, *vh;
    float *sxx, *pk2, *pxk, *pv2, *scale;
    cudaGetSymbolAddress((void**)&xh,    g_xh);
    cudaGetSymbolAddress((void**)&winh,  g_winh);
    cudaGetSymbolAddress((void**)&wkh,   g_wkh);
    cudaGetSymbolAddress((void**)&wvh,   g_wvh);
    cudaGetSymbolAddress((void**)&wch,   g_wch);
    cudaGetSymbolAddress((void**)&zh,    g_zh);
    cudaGetSymbolAddress((void**)&zm,    g_zm);
    cudaGetSymbolAddress((void**)&yh,    g_yh);
    cudaGetSymbolAddress((void**)&vh,    g_vh);
    cudaGetSymbolAddress((void**)&sxx,   g_sxx);
    cudaGetSymbolAddress((void**)&pk2,   g_pk2);
    cudaGetSymbolAddress((void**)&pxk,   g_pxk);
    cudaGetSymbolAddress((void**)&pv2,   g_pv2);
    cudaGetSymbolAddress((void**)&scale, g_scale);

    cudaFuncSetAttribute(gemm_f16,
                         cudaFuncAttributeMaxDynamicSharedMemorySize, GEMM_SMEM);
    cudaFuncSetAttribute(gemm_kv,
                         cudaFuncAttributeMaxDynamicSharedMemorySize, GEMM_SMEM);

    // 0) fused prep: x->fp16(+sum x^2), 3 weight conversions, wmix combine
    prep<<<BT + 768 + 512, 128>>>(x, xh, sxx, W_in, winh, W_k, wkh,
                                  W_v, wvh, W_mix, wch);

    // 1) z = xh @ winh^T -> fp16
    gemm_f16<<<dim3(DBDIM / TBN, BT / TBM, 1), 256, GEMM_SMEM>>>(
        xh, winh, winh, zh, zh, DBDIM, DDIM);

    // 2) zm = zh @ wch^T -> fp16
    gemm_f16<<<dim3(3 * DBDIM / TBN, BT / TBM, 1), 256, GEMM_SMEM>>>(
        zh, wch, wch, zm, zm, 3 * DBDIM, DBDIM);

    // 3) y gather -> fp16
    build_y<<<BT, 128>>>(zm, doc, yh);

    // 4) fused k/v: z=0 -> gate partials (k never stored); z=1 -> vh + v^2
    gemm_kv<<<dim3(DDIM / TBN, BT / TBM, 2), 256, GEMM_SMEM>>>(
        yh, wkh, wvh, vh, xh, pk2, pxk, pv2, DDIM, DBDIM);

    // 5) combine partials -> per-token scale
    gate_combine<<<BT / 256, 256>>>(sxx, pk2, pxk, pv2, scale);

    // 6) depthwise causal conv + SiLU -> final fp32 output
    conv_silu<<<BT, 256>>>(vh, scale, doc, conv_w, out);
}